// round 5
// baseline (speedup 1.0000x reference)
#include <cuda_runtime.h>
#include <cuda_bf16.h>

// Shapes: B=32, S=2048, I=128, A=128, H=256, K=8, ACTIVE=3 (structurally k=0,1,2)
#define NB 32
#define NS 2048
#define NI 128
#define NA 128
#define NH 256
#define NK 8
#define KACT 3
#define CHUNKS 16
#define ROWS_PER_BLOCK (NS / CHUNKS)       // 128
#define ROWS_PER_WARP (ROWS_PER_BLOCK / 8) // 16

#define NBLK_Q    (KACT * 4)               // 12: q partials
#define NBLK_U    (KACT)                   // 3 : u
#define NBLK_H    (KACT * 4)               // 12: hpre
#define NBLK_PRE  (NBLK_Q + NBLK_U + NBLK_H)      // 27
#define NBLK_MAIN (NB * CHUNKS)            // 512
#define NBLK      (NBLK_PRE + NBLK_MAIN)   // 539

// Device scratch (allocation-free rule: __device__ globals; zero-initialized)
__device__ float g_qpart[KACT][4][NA];
__device__ float g_u[KACT][NI];
__device__ float g_hpre[KACT][NH];
__device__ float g_ypart[NB][CHUNKS][KACT * NI];
__device__ int   g_qcnt[KACT];
__device__ int   g_ucnt;
__device__ int   g_hcnt;
__device__ int   g_bcnt[NB];
__device__ int   g_done;

__device__ __forceinline__ void spin_until(int* p, int target) {
    while (*(volatile int*)p < target) __nanosleep(32);
}

__global__ __launch_bounds__(256) void fused_kernel(
    const float* __restrict__ x,   const float* __restrict__ rim,
    const float* __restrict__ Wq,  const float* __restrict__ Wk,
    const float* __restrict__ Wv,  const float* __restrict__ Wih,
    const float* __restrict__ Whh, const float* __restrict__ bias,
    float* __restrict__ out)
{
    const int tid = threadIdx.x;
    const int bid = blockIdx.x;
    __shared__ __align__(16) float pool[8 * KACT * NI];  // 12 KB, reused per role

    if (bid < NBLK_Q) {
        // ---- q partials: block (k, p), h in [p*64, p*64+64); 128a x 2sub x 32 loads
        const int k = bid >> 2, p = bid & 3;
        const int a = tid & 127, sub = tid >> 7;
        const int h0 = p * 64 + sub * 32;
        const float* __restrict__ wq = Wq + ((size_t)(k * NH + h0)) * NA + a;
        const float* __restrict__ rk = rim + k * NH + h0;
        float acc0 = 0.f, acc1 = 0.f, acc2 = 0.f, acc3 = 0.f;
        #pragma unroll
        for (int h = 0; h < 32; h += 4) {
            acc0 += rk[h + 0] * wq[(size_t)(h + 0) * NA];
            acc1 += rk[h + 1] * wq[(size_t)(h + 1) * NA];
            acc2 += rk[h + 2] * wq[(size_t)(h + 2) * NA];
            acc3 += rk[h + 3] * wq[(size_t)(h + 3) * NA];
        }
        float (*qp)[NA] = (float(*)[NA])pool;
        qp[sub][a] = (acc0 + acc1) + (acc2 + acc3);
        __syncthreads();
        if (tid < NA) g_qpart[k][p][tid] = qp[0][tid] + qp[1][tid];
        __threadfence();
        __syncthreads();
        if (tid == 0) atomicAdd(&g_qcnt[k], 1);
    } else if (bid < NBLK_Q + NBLK_U) {
        // ---- u[k][i] = Wk[k][i][:].q : prefetch Wk rows, spin for q, combine, dot
        const int k = bid - NBLK_Q;
        const int warp = tid >> 5, lane = tid & 31;
        const float4* __restrict__ wkbase =
            reinterpret_cast<const float4*>(Wk + ((size_t)k * NI) * NA);
        float4 w4[16];
        #pragma unroll
        for (int ii = 0; ii < 16; ++ii)
            w4[ii] = wkbase[(size_t)(warp * 16 + ii) * 32 + lane];

        if (tid == 0) spin_until(&g_qcnt[k], 4);
        __syncthreads();

        float* qs = pool;
        if (tid < NA) {
            float s = (__ldcg(&g_qpart[k][0][tid]) + __ldcg(&g_qpart[k][1][tid]))
                    + (__ldcg(&g_qpart[k][2][tid]) + __ldcg(&g_qpart[k][3][tid]));
            qs[tid] = s;
        }
        __syncthreads();
        const float4 q4 = reinterpret_cast<const float4*>(qs)[lane];
        #pragma unroll
        for (int ii = 0; ii < 16; ++ii) {
            float p = w4[ii].x * q4.x + w4[ii].y * q4.y + w4[ii].z * q4.z + w4[ii].w * q4.w;
            #pragma unroll
            for (int off = 16; off; off >>= 1) p += __shfl_xor_sync(0xffffffffu, p, off);
            if (lane == 0) g_u[k][warp * 16 + ii] = p;
        }
        __threadfence();
        __syncthreads();
        if (tid == 0) atomicAdd(&g_ucnt, 1);
    } else if (bid < NBLK_PRE) {
        // ---- hpre: block (k, hq), h = hq*64 + tid&63, part = tid>>6 (4x64 hp)
        const int idx = bid - NBLK_Q - NBLK_U;
        const int k = idx >> 2, hq = idx & 3;
        const int h = hq * 64 + (tid & 63);
        const int part = tid >> 6;
        const float* __restrict__ rk = rim + k * NH + part * 64;
        const float* __restrict__ wh = Whh + (size_t)(part * 64) * NH + h;
        float acc0 = 0.f, acc1 = 0.f, acc2 = 0.f, acc3 = 0.f;
        #pragma unroll
        for (int hp = 0; hp < 64; hp += 4) {
            acc0 += rk[hp + 0] * wh[(size_t)(hp + 0) * NH];
            acc1 += rk[hp + 1] * wh[(size_t)(hp + 1) * NH];
            acc2 += rk[hp + 2] * wh[(size_t)(hp + 2) * NH];
            acc3 += rk[hp + 3] * wh[(size_t)(hp + 3) * NH];
        }
        float (*hs)[64] = (float(*)[64])pool;
        hs[part][tid & 63] = (acc0 + acc1) + (acc2 + acc3);
        __syncthreads();
        if (tid < 64) {
            g_hpre[k][h] = bias[h] +
                ((hs[0][tid] + hs[1][tid]) + (hs[2][tid] + hs[3][tid]));
        }
        __threadfence();
        __syncthreads();
        if (tid == 0) atomicAdd(&g_hcnt, 1);
    } else {
        // ================= MAIN =================
        const int mb    = bid - NBLK_PRE;
        const int b     = mb >> 4;
        const int chunk = mb & 15;
        const int warp  = tid >> 5;
        const int lane  = tid & 31;

        const size_t row0 = (size_t)b * NS + chunk * ROWS_PER_BLOCK + warp * ROWS_PER_WARP;
        const float4* __restrict__ xr = reinterpret_cast<const float4*>(x + row0 * NI) + lane;

        // prefetch all 16 x-vectors into registers (in flight during spin)
        float4 xv[ROWS_PER_WARP];
        #pragma unroll
        for (int r = 0; r < ROWS_PER_WARP; ++r) xv[r] = xr[r * 32];

        if (tid == 0) spin_until(&g_ucnt, KACT);
        __syncthreads();

        const float4 u0 = __ldcg(&reinterpret_cast<const float4*>(g_u[0])[lane]);
        const float4 u1 = __ldcg(&reinterpret_cast<const float4*>(g_u[1])[lane]);
        const float4 u2 = __ldcg(&reinterpret_cast<const float4*>(g_u[2])[lane]);

        float4 a0 = make_float4(0.f, 0.f, 0.f, 0.f);
        float4 a1 = a0, a2 = a0;

        #pragma unroll
        for (int r = 0; r < ROWS_PER_WARP; ++r) {
            const float4 v = xv[r];
            float d0 = v.x * u0.x + v.y * u0.y + v.z * u0.z + v.w * u0.w;
            float d1 = v.x * u1.x + v.y * u1.y + v.z * u1.z + v.w * u1.w;
            float d2 = v.x * u2.x + v.y * u2.y + v.z * u2.z + v.w * u2.w;
            #pragma unroll
            for (int off = 16; off; off >>= 1) {
                d0 += __shfl_xor_sync(0xffffffffu, d0, off);
                d1 += __shfl_xor_sync(0xffffffffu, d1, off);
                d2 += __shfl_xor_sync(0xffffffffu, d2, off);
            }
            a0.x += d0 * v.x; a0.y += d0 * v.y; a0.z += d0 * v.z; a0.w += d0 * v.w;
            a1.x += d1 * v.x; a1.y += d1 * v.y; a1.z += d1 * v.z; a1.w += d1 * v.w;
            a2.x += d2 * v.x; a2.y += d2 * v.y; a2.z += d2 * v.z; a2.w += d2 * v.w;
        }

        float (*ysw)[KACT * NI] = (float(*)[KACT * NI])pool;
        reinterpret_cast<float4*>(&ysw[warp][0 * NI])[lane] = a0;
        reinterpret_cast<float4*>(&ysw[warp][1 * NI])[lane] = a1;
        reinterpret_cast<float4*>(&ysw[warp][2 * NI])[lane] = a2;
        __syncthreads();

        float* yp = g_ypart[b][chunk];
        for (int idx = tid; idx < KACT * NI; idx += 256) {
            float s = 0.f;
            #pragma unroll
            for (int w = 0; w < 8; ++w) s += ysw[w][idx];
            yp[idx] = s;
        }
        __threadfence();
        __syncthreads();

        // ---- election: last block of this b runs the epilogue
        __shared__ int elect;
        if (tid == 0) elect = (atomicAdd(&g_bcnt[b], 1) == CHUNKS - 1) ? 1 : 0;
        __syncthreads();

        if (elect) {
            if (tid == 0) spin_until(&g_hcnt, NBLK_H);
            __syncthreads();

            float* ys   = pool;             // 384
            float* attp = pool + 384;       // 768
            float* att  = pool + 1152;      // 384

            // y: 384 outputs, 16 ldcg loads each
            for (int j = tid; j < KACT * NI; j += 256) {
                const float* ypb = &g_ypart[b][0][0];
                float s0 = __ldcg(ypb + 0 * (KACT * NI) + j);
                float s1 = __ldcg(ypb + 1 * (KACT * NI) + j);
                float s2 = __ldcg(ypb + 2 * (KACT * NI) + j);
                float s3 = __ldcg(ypb + 3 * (KACT * NI) + j);
                #pragma unroll
                for (int c = 4; c < CHUNKS; c += 4) {
                    s0 += __ldcg(ypb + (c + 0) * (KACT * NI) + j);
                    s1 += __ldcg(ypb + (c + 1) * (KACT * NI) + j);
                    s2 += __ldcg(ypb + (c + 2) * (KACT * NI) + j);
                    s3 += __ldcg(ypb + (c + 3) * (KACT * NI) + j);
                }
                ys[j] = (s0 + s1) + (s2 + s3);
            }
            __syncthreads();

            // att: 768 half-tasks, 64-long reduce each
            for (int t = tid; t < 2 * KACT * NA; t += 256) {
                const int half = t / (KACT * NA);
                const int jj = t - half * (KACT * NA);
                const int k = jj >> 7, a = jj & 127;
                const float* __restrict__ wv =
                    Wv + (size_t)k * NI * NA + (size_t)(half * 64) * NA + a;
                const float* __restrict__ yk = ys + k * NI + half * 64;
                float c0 = 0.f, c1 = 0.f, c2 = 0.f, c3 = 0.f;
                #pragma unroll
                for (int i = 0; i < 64; i += 4) {
                    c0 += wv[(size_t)(i + 0) * NA] * yk[i + 0];
                    c1 += wv[(size_t)(i + 1) * NA] * yk[i + 1];
                    c2 += wv[(size_t)(i + 2) * NA] * yk[i + 2];
                    c3 += wv[(size_t)(i + 3) * NA] * yk[i + 3];
                }
                attp[t] = (c0 + c1) + (c2 + c3);
            }
            __syncthreads();
            for (int j = tid; j < KACT * NA; j += 256)
                att[j] = attp[j] + attp[KACT * NA + j];
            __syncthreads();

            float* ob = out + (size_t)b * NK * NH;
            // cand: 768 outputs, 128-long reduce
            for (int t = tid; t < KACT * NH; t += 256) {
                const int k = t >> 8, h = t & 255;
                const float* __restrict__ ak = att + k * NA;
                const float* __restrict__ wih = Wih + h;
                float c0 = __ldcg(&g_hpre[k][h]), c1 = 0.f, c2 = 0.f, c3 = 0.f;
                #pragma unroll
                for (int a = 0; a < NA; a += 4) {
                    c0 += ak[a + 0] * wih[(size_t)(a + 0) * NH];
                    c1 += ak[a + 1] * wih[(size_t)(a + 1) * NH];
                    c2 += ak[a + 2] * wih[(size_t)(a + 2) * NH];
                    c3 += ak[a + 3] * wih[(size_t)(a + 3) * NH];
                }
                ob[t] = tanhf((c0 + c1) + (c2 + c3));
            }
            // k = 3..7: passthrough
            for (int j = tid; j < (NK - KACT) * NH; j += 256)
                ob[KACT * NH + j] = rim[KACT * NH + j];
        }
    }

    // ---- done-counter; last block resets all flags for the next graph replay
    __syncthreads();
    if (tid == 0) {
        const int old = atomicAdd(&g_done, 1);
        if (old == NBLK - 1) {
            #pragma unroll
            for (int k = 0; k < KACT; ++k) g_qcnt[k] = 0;
            g_ucnt = 0;
            g_hcnt = 0;
            #pragma unroll
            for (int b2 = 0; b2 < NB; ++b2) g_bcnt[b2] = 0;
            g_done = 0;
        }
    }
}

// ---------------------------------------------------------------------------
extern "C" void kernel_launch(void* const* d_in, const int* in_sizes, int n_in,
                              void* d_out, int out_size)
{
    const float* x    = (const float*)d_in[0];
    const float* rim  = (const float*)d_in[1];
    const float* Wq   = (const float*)d_in[2];
    const float* Wk   = (const float*)d_in[3];
    const float* Wv   = (const float*)d_in[4];
    const float* Wih  = (const float*)d_in[5];
    const float* Whh  = (const float*)d_in[6];
    const float* bias = (const float*)d_in[7];
    float* out = (float*)d_out;

    fused_kernel<<<NBLK, 256>>>(x, rim, Wq, Wk, Wv, Wih, Whh, bias, out);
}

// round 6
// speedup vs baseline: 1.3801x; 1.3801x over previous
#include <cuda_runtime.h>
#include <cuda_bf16.h>

// Shapes: B=32, S=2048, I=128, A=128, H=256, K=8, ACTIVE=3 (structurally k=0,1,2)
#define NB 32
#define NS 2048
#define NI 128
#define NA 128
#define NH 256
#define NK 8
#define KACT 3
#define CHUNKS 16
#define ROWS_PER_BLOCK (NS / CHUNKS)       // 128
#define ROWS_PER_WARP (ROWS_PER_BLOCK / 8) // 16
#define PREF 4                              // prefetched rows per warp

#define NBLK_Q    (KACT * 4)               // 12: q partials
#define NBLK_U    (KACT)                   // 3 : u
#define NBLK_H    (KACT * 4)               // 12: hpre
#define NBLK_PRE  (NBLK_Q + NBLK_U + NBLK_H)      // 27
#define NBLK_MAIN (NB * CHUNKS)            // 512
#define NBLK      (NBLK_PRE + NBLK_MAIN)   // 539

// Device scratch (allocation-free rule: __device__ globals; zero-initialized)
__device__ float g_qpart[KACT][4][NA];
__device__ float g_u[KACT][NI];
__device__ float g_hpre[KACT][NH];
__device__ float g_ypart[NB][CHUNKS][KACT * NI];
__device__ int   g_qcnt[KACT];
__device__ int   g_ucnt;

__device__ __forceinline__ void spin_until(int* p, int target) {
    while (*(volatile int*)p < target) __nanosleep(32);
}

// ===========================================================================
// Kernel A: prologue (27 blocks) + main (512 blocks), intra-grid flag sync.
// ===========================================================================
__global__ __launch_bounds__(256) void fused_main_kernel(
    const float* __restrict__ x,   const float* __restrict__ rim,
    const float* __restrict__ Wq,  const float* __restrict__ Wk,
    const float* __restrict__ Whh, const float* __restrict__ bias)
{
    const int tid = threadIdx.x;
    const int bid = blockIdx.x;
    __shared__ __align__(16) float pool[8 * KACT * NI];  // 12 KB, reused per role

    if (bid >= NBLK_PRE) {
        // ================= MAIN =================
        const int mb    = bid - NBLK_PRE;
        const int b     = mb >> 4;
        const int chunk = mb & 15;
        const int warp  = tid >> 5;
        const int lane  = tid & 31;

        const size_t row0 = (size_t)b * NS + chunk * ROWS_PER_BLOCK + warp * ROWS_PER_WARP;
        const float4* __restrict__ xr = reinterpret_cast<const float4*>(x + row0 * NI) + lane;

        // small prefetch keeps DRAM/L2 busy while prologue finishes
        float4 xv[PREF];
        #pragma unroll
        for (int r = 0; r < PREF; ++r) xv[r] = xr[r * 32];

        if (tid == 0) spin_until(&g_ucnt, KACT);
        __syncthreads();

        const float4 u0 = __ldcg(&reinterpret_cast<const float4*>(g_u[0])[lane]);
        const float4 u1 = __ldcg(&reinterpret_cast<const float4*>(g_u[1])[lane]);
        const float4 u2 = __ldcg(&reinterpret_cast<const float4*>(g_u[2])[lane]);

        float4 a0 = make_float4(0.f, 0.f, 0.f, 0.f);
        float4 a1 = a0, a2 = a0;

        #pragma unroll
        for (int r = 0; r < ROWS_PER_WARP; ++r) {
            const float4 v = (r < PREF) ? xv[r] : xr[r * 32];
            float d0 = v.x * u0.x + v.y * u0.y + v.z * u0.z + v.w * u0.w;
            float d1 = v.x * u1.x + v.y * u1.y + v.z * u1.z + v.w * u1.w;
            float d2 = v.x * u2.x + v.y * u2.y + v.z * u2.z + v.w * u2.w;
            #pragma unroll
            for (int off = 16; off; off >>= 1) {
                d0 += __shfl_xor_sync(0xffffffffu, d0, off);
                d1 += __shfl_xor_sync(0xffffffffu, d1, off);
                d2 += __shfl_xor_sync(0xffffffffu, d2, off);
            }
            a0.x += d0 * v.x; a0.y += d0 * v.y; a0.z += d0 * v.z; a0.w += d0 * v.w;
            a1.x += d1 * v.x; a1.y += d1 * v.y; a1.z += d1 * v.z; a1.w += d1 * v.w;
            a2.x += d2 * v.x; a2.y += d2 * v.y; a2.z += d2 * v.z; a2.w += d2 * v.w;
        }

        float (*ysw)[KACT * NI] = (float(*)[KACT * NI])pool;
        reinterpret_cast<float4*>(&ysw[warp][0 * NI])[lane] = a0;
        reinterpret_cast<float4*>(&ysw[warp][1 * NI])[lane] = a1;
        reinterpret_cast<float4*>(&ysw[warp][2 * NI])[lane] = a2;
        __syncthreads();

        float* yp = g_ypart[b][chunk];
        for (int idx = tid; idx < KACT * NI; idx += 256) {
            float s = 0.f;
            #pragma unroll
            for (int w = 0; w < 8; ++w) s += ysw[w][idx];
            yp[idx] = s;
        }
    } else if (bid < NBLK_Q) {
        // ---- q partials: block (k, p), h in [p*64, p*64+64); 128a x 2sub x 32 loads
        const int k = bid >> 2, p = bid & 3;
        const int a = tid & 127, sub = tid >> 7;
        const int h0 = p * 64 + sub * 32;
        const float* __restrict__ wq = Wq + ((size_t)(k * NH + h0)) * NA + a;
        const float* __restrict__ rk = rim + k * NH + h0;
        float acc0 = 0.f, acc1 = 0.f, acc2 = 0.f, acc3 = 0.f;
        #pragma unroll
        for (int h = 0; h < 32; h += 4) {
            acc0 += rk[h + 0] * wq[(size_t)(h + 0) * NA];
            acc1 += rk[h + 1] * wq[(size_t)(h + 1) * NA];
            acc2 += rk[h + 2] * wq[(size_t)(h + 2) * NA];
            acc3 += rk[h + 3] * wq[(size_t)(h + 3) * NA];
        }
        float (*qp)[NA] = (float(*)[NA])pool;
        qp[sub][a] = (acc0 + acc1) + (acc2 + acc3);
        __syncthreads();
        if (tid < NA) g_qpart[k][p][tid] = qp[0][tid] + qp[1][tid];
        __threadfence();
        __syncthreads();
        if (tid == 0) atomicAdd(&g_qcnt[k], 1);
    } else if (bid < NBLK_Q + NBLK_U) {
        // ---- u[k][i] = Wk[k][i][:].q : prefetch Wk rows, spin for q, combine, dot
        const int k = bid - NBLK_Q;
        const int warp = tid >> 5, lane = tid & 31;
        const float4* __restrict__ wkbase =
            reinterpret_cast<const float4*>(Wk + ((size_t)k * NI) * NA);
        float4 w4[16];
        #pragma unroll
        for (int ii = 0; ii < 16; ++ii)
            w4[ii] = wkbase[(size_t)(warp * 16 + ii) * 32 + lane];

        if (tid == 0) spin_until(&g_qcnt[k], 4);
        __syncthreads();

        float* qs = pool;
        if (tid < NA) {
            qs[tid] = (__ldcg(&g_qpart[k][0][tid]) + __ldcg(&g_qpart[k][1][tid]))
                    + (__ldcg(&g_qpart[k][2][tid]) + __ldcg(&g_qpart[k][3][tid]));
        }
        __syncthreads();
        const float4 q4 = reinterpret_cast<const float4*>(qs)[lane];
        #pragma unroll
        for (int ii = 0; ii < 16; ++ii) {
            float p = w4[ii].x * q4.x + w4[ii].y * q4.y + w4[ii].z * q4.z + w4[ii].w * q4.w;
            #pragma unroll
            for (int off = 16; off; off >>= 1) p += __shfl_xor_sync(0xffffffffu, p, off);
            if (lane == 0) g_u[k][warp * 16 + ii] = p;
        }
        __threadfence();
        __syncthreads();
        if (tid == 0) atomicAdd(&g_ucnt, 1);
    } else {
        // ---- hpre: block (k, hq), h = hq*64 + tid&63, part = tid>>6 (4x64 hp)
        // consumed only by the epilogue kernel (next graph node) — no flag needed
        const int idx = bid - NBLK_Q - NBLK_U;
        const int k = idx >> 2, hq = idx & 3;
        const int h = hq * 64 + (tid & 63);
        const int part = tid >> 6;
        const float* __restrict__ rk = rim + k * NH + part * 64;
        const float* __restrict__ wh = Whh + (size_t)(part * 64) * NH + h;
        float acc0 = 0.f, acc1 = 0.f, acc2 = 0.f, acc3 = 0.f;
        #pragma unroll
        for (int hp = 0; hp < 64; hp += 4) {
            acc0 += rk[hp + 0] * wh[(size_t)(hp + 0) * NH];
            acc1 += rk[hp + 1] * wh[(size_t)(hp + 1) * NH];
            acc2 += rk[hp + 2] * wh[(size_t)(hp + 2) * NH];
            acc3 += rk[hp + 3] * wh[(size_t)(hp + 3) * NH];
        }
        float (*hs)[64] = (float(*)[64])pool;
        hs[part][tid & 63] = (acc0 + acc1) + (acc2 + acc3);
        __syncthreads();
        if (tid < 64) {
            g_hpre[k][h] = bias[h] +
                ((hs[0][tid] + hs[1][tid]) + (hs[2][tid] + hs[3][tid]));
        }
    }
}

// ===========================================================================
// Kernel B: epilogue (32 blocks x 1024). Runs after A completes (stream order).
// Block 0 also resets A's sync counters for the next graph replay.
// ===========================================================================
__global__ __launch_bounds__(1024) void epilogue_kernel(
    const float* __restrict__ rim, const float* __restrict__ Wv,
    const float* __restrict__ Wih, float* __restrict__ out)
{
    const int b = blockIdx.x;
    const int tid = threadIdx.x;

    if (b == 0 && tid < 4) {        // reset flags (A is fully done; B precedes next A)
        if (tid < KACT) g_qcnt[tid] = 0;
        else            g_ucnt = 0;
    }

    __shared__ float ys[KACT * NI];
    __shared__ float attp[2][KACT * NA];
    __shared__ float att[KACT * NA];

    // ---- y: 384 outputs, 16 fully-unrolled loads each (1 batch)
    if (tid < KACT * NI) {
        const float* yp = &g_ypart[b][0][0];
        float s0 = yp[0 * (KACT * NI) + tid];
        float s1 = yp[1 * (KACT * NI) + tid];
        float s2 = yp[2 * (KACT * NI) + tid];
        float s3 = yp[3 * (KACT * NI) + tid];
        #pragma unroll
        for (int c = 4; c < CHUNKS; c += 4) {
            s0 += yp[(c + 0) * (KACT * NI) + tid];
            s1 += yp[(c + 1) * (KACT * NI) + tid];
            s2 += yp[(c + 2) * (KACT * NI) + tid];
            s3 += yp[(c + 3) * (KACT * NI) + tid];
        }
        ys[tid] = (s0 + s1) + (s2 + s3);
    }
    __syncthreads();

    // ---- att[k][a] = sum_i Wv[k][i][a]*ys[k][i]; 2-way split over i
    if (tid < 2 * KACT * NA) {
        const int half = tid / (KACT * NA);
        const int jj   = tid - half * (KACT * NA);
        const int k = jj >> 7, a = jj & 127;
        const float* __restrict__ wv =
            Wv + (size_t)k * NI * NA + (size_t)(half * 64) * NA + a;
        const float* __restrict__ yk = ys + k * NI + half * 64;
        float c0 = 0.f, c1 = 0.f, c2 = 0.f, c3 = 0.f;
        #pragma unroll
        for (int i = 0; i < 64; i += 4) {
            c0 += wv[(size_t)(i + 0) * NA] * yk[i + 0];
            c1 += wv[(size_t)(i + 1) * NA] * yk[i + 1];
            c2 += wv[(size_t)(i + 2) * NA] * yk[i + 2];
            c3 += wv[(size_t)(i + 3) * NA] * yk[i + 3];
        }
        attp[half][jj] = (c0 + c1) + (c2 + c3);
    }
    __syncthreads();
    if (tid < KACT * NA) att[tid] = attp[0][tid] + attp[1][tid];
    __syncthreads();

    float* ob = out + (size_t)b * NK * NH;

    // ---- cand: 768 outputs, one thread each, 128-long reduce
    if (tid < KACT * NH) {
        const int k = tid >> 8, h = tid & 255;
        const float* __restrict__ ak = att + k * NA;
        const float* __restrict__ wih = Wih + h;
        float c0 = g_hpre[k][h], c1 = 0.f, c2 = 0.f, c3 = 0.f;
        #pragma unroll
        for (int a = 0; a < NA; a += 4) {
            c0 += ak[a + 0] * wih[(size_t)(a + 0) * NH];
            c1 += ak[a + 1] * wih[(size_t)(a + 1) * NH];
            c2 += ak[a + 2] * wih[(size_t)(a + 2) * NH];
            c3 += ak[a + 3] * wih[(size_t)(a + 3) * NH];
        }
        ob[tid] = tanhf((c0 + c1) + (c2 + c3));
    }
    // ---- k = 3..7: passthrough rim_hidden (1280 floats)
    for (int j = tid; j < (NK - KACT) * NH; j += 1024) {
        ob[KACT * NH + j] = rim[KACT * NH + j];
    }
}

// ---------------------------------------------------------------------------
extern "C" void kernel_launch(void* const* d_in, const int* in_sizes, int n_in,
                              void* d_out, int out_size)
{
    const float* x    = (const float*)d_in[0];
    const float* rim  = (const float*)d_in[1];
    const float* Wq   = (const float*)d_in[2];
    const float* Wk   = (const float*)d_in[3];
    const float* Wv   = (const float*)d_in[4];
    const float* Wih  = (const float*)d_in[5];
    const float* Whh  = (const float*)d_in[6];
    const float* bias = (const float*)d_in[7];
    float* out = (float*)d_out;

    fused_main_kernel<<<NBLK, 256>>>(x, rim, Wq, Wk, Whh, bias);
    epilogue_kernel<<<NB, 1024>>>(rim, Wv, Wih, out);
}